// round 13
// baseline (speedup 1.0000x reference)
#include <cuda_runtime.h>
#include <cuda_fp16.h>
#include <cstddef>

// BilinearMixture: out[e,c] = sum_w (sum_d u[ui,d]*W[w,d]*v[vi,d]) * scalars[w,c]
//                           + u_bias[ui,c] + v_bias[vi,c]
// E=2e6, D=128, NUM_W=3, C=5.
//
// Phase 1: convert u/v tables + W to fp16 scratch (51 MB -> L2-resident).
// Phase 2: 8 lanes/edge, 4 groups, 2 edges/thread (8 edges/warp):
//   - features: 4 wf/edge; u*v via HMUL2 then cvt
//   - W unpacked once/iter, shared by both edges
//   - NEW: accumulation via Blackwell packed fma.rn.f32x2 (FFMA2):
//     24 FFMA2/edge instead of 48 FFMA, identical fp32 precision.

#define D 128
#define NUM_W 3
#define NUM_C 5
#define NUM_USERS 100000
#define NUM_ITEMS 100000
#define THREADS 256
#define WARPS_PER_BLOCK (THREADS / 32)
#define EDGES_PER_WARP 8
#define EDGES_PER_BLOCK (WARPS_PER_BLOCK * EDGES_PER_WARP)  // 64

#define ROW_U4 (D / 8)            // 16 uint4 per 128-half row
__device__ uint4 g_u16[(size_t)NUM_USERS * ROW_U4];
__device__ uint4 g_v16[(size_t)NUM_ITEMS * ROW_U4];
__device__ uint4 g_w16[NUM_W * ROW_U4];     // 48 uint4

// ---------------- packed f32x2 helpers ----------------
typedef unsigned long long u64;

__device__ __forceinline__ u64 pack2(float lo, float hi) {
    u64 r;
    asm("mov.b64 %0, {%1, %2};" : "=l"(r) : "f"(lo), "f"(hi));
    return r;
}
__device__ __forceinline__ void unpack2(u64 p, float& lo, float& hi) {
    asm("mov.b64 {%0, %1}, %2;" : "=f"(lo), "=f"(hi) : "l"(p));
}
__device__ __forceinline__ u64 ffma2(u64 a, u64 b, u64 c) {
    u64 d;
    asm("fma.rn.f32x2 %0, %1, %2, %3;" : "=l"(d) : "l"(a), "l"(b), "l"(c));
    return d;
}

// uint4 of 8 halves -> 4 packed f32x2.
__device__ __forceinline__ void h8_to_p4(const uint4& r, u64* p) {
    const __half2* h = reinterpret_cast<const __half2*>(&r);
#pragma unroll
    for (int k = 0; k < 4; k++) {
        float2 t = __half22float2(h[k]);
        p[k] = pack2(t.x, t.y);
    }
}
// p[k] = packed f32x2 of (u ⊙ v) for 8 halves: 4 HMUL2 + cvt + pack.
__device__ __forceinline__ void hprod_to_p4(const uint4& u, const uint4& v, u64* p) {
    const __half2* uh = reinterpret_cast<const __half2*>(&u);
    const __half2* vh = reinterpret_cast<const __half2*>(&v);
#pragma unroll
    for (int k = 0; k < 4; k++) {
        __half2 q = __hmul2(uh[k], vh[k]);
        float2 t = __half22float2(q);
        p[k] = pack2(t.x, t.y);
    }
}

// ---------------- conversion kernel: fp32 -> fp16 ----------------
__global__ __launch_bounds__(256)
void convert_kernel(const float4* __restrict__ u_src,
                    const float4* __restrict__ v_src,
                    const float4* __restrict__ w_src,
                    int n_u, int n_v, int n_w)   // uint4 counts
{
    const int total = n_u + n_v + n_w;
    for (int idx = blockIdx.x * blockDim.x + threadIdx.x; idx < total;
         idx += gridDim.x * blockDim.x)
    {
        const float4* s;
        uint4* dst;
        int j;
        if (idx < n_u)              { s = u_src; dst = g_u16; j = idx; }
        else if (idx < n_u + n_v)   { s = v_src; dst = g_v16; j = idx - n_u; }
        else                        { s = w_src; dst = g_w16; j = idx - n_u - n_v; }
        const float4 a = s[2 * j];
        const float4 b = s[2 * j + 1];
        __half2 h0 = __floats2half2_rn(a.x, a.y);
        __half2 h1 = __floats2half2_rn(a.z, a.w);
        __half2 h2 = __floats2half2_rn(b.x, b.y);
        __half2 h3 = __floats2half2_rn(b.z, b.w);
        uint4 o;
        o.x = *reinterpret_cast<unsigned*>(&h0);
        o.y = *reinterpret_cast<unsigned*>(&h1);
        o.z = *reinterpret_cast<unsigned*>(&h2);
        o.w = *reinterpret_cast<unsigned*>(&h3);
        dst[j] = o;
    }
}

// ---------------- main kernel ----------------
__global__ __launch_bounds__(THREADS, 3)
void bilinear_mixture_kernel(
    const int*   __restrict__ u_idx,
    const int*   __restrict__ v_idx,
    const float* __restrict__ scalars,
    const float* __restrict__ u_bias,
    const float* __restrict__ v_bias,
    float*       __restrict__ out,
    int E)
{
    const int tid  = threadIdx.x;
    const int lane = tid & 31;
    const int l    = lane & 7;        // lane within edge-group (0..7)
    const int g    = lane >> 3;       // edge-group within warp (0..3)
    const int warp = tid >> 5;

    const int ebase = blockIdx.x * EDGES_PER_BLOCK + warp * EDGES_PER_WARP;
    const int e0 = ebase + g;       // quad A edge
    const int e1 = ebase + 4 + g;   // quad B edge
    const bool val0 = (e0 < E);
    const bool val1 = (e1 < E);

    const int ui0 = val0 ? u_idx[e0] : 0;
    const int vi0 = val0 ? v_idx[e0] : 0;
    const int ui1 = val1 ? u_idx[e1] : 0;
    const int vi1 = val1 ? v_idx[e1] : 0;

    const uint4* up0 = g_u16 + (size_t)ui0 * ROW_U4;
    const uint4* vp0 = g_v16 + (size_t)vi0 * ROW_U4;
    const uint4* up1 = g_u16 + (size_t)ui1 * ROW_U4;
    const uint4* vp1 = g_v16 + (size_t)vi1 * ROW_U4;

    // All 8 feature loads issued up front (MLP 8/lane, 4 wf/edge).
    uint4 ua[2], va[2], ub4[2], vb4[2];
#pragma unroll
    for (int i = 0; i < 2; i++) {
        ua[i]  = up0[i * 8 + l];
        va[i]  = vp0[i * 8 + l];
        ub4[i] = up1[i * 8 + l];
        vb4[i] = vp1[i * 8 + l];
    }

    // Per-class constants + bias gathers (overlap with outstanding loads).
    float s0 = 0.f, s1 = 0.f, s2 = 0.f;
    float ubias0 = 0.f, vbias0 = 0.f, ubias1 = 0.f, vbias1 = 0.f;
    if (l < NUM_C) {
        s0 = __ldg(scalars + 0 * NUM_C + l);
        s1 = __ldg(scalars + 1 * NUM_C + l);
        s2 = __ldg(scalars + 2 * NUM_C + l);
        ubias0 = __ldg(u_bias + (size_t)ui0 * NUM_C + l);
        vbias0 = __ldg(v_bias + (size_t)vi0 * NUM_C + l);
        ubias1 = __ldg(u_bias + (size_t)ui1 * NUM_C + l);
        vbias1 = __ldg(v_bias + (size_t)vi1 * NUM_C + l);
    }

    const u64 zero = pack2(0.f, 0.f);
    u64 A0 = zero, A1 = zero, A2 = zero;   // quad A packed accumulators
    u64 C0 = zero, C1 = zero, C2 = zero;   // quad B packed accumulators

#pragma unroll
    for (int i = 0; i < 2; i++) {
        // W fp16 broadcast loads (1 wf each), unpacked ONCE, shared by both edges.
        const uint4 w0 = g_w16[0 * ROW_U4 + i * 8 + l];
        const uint4 w1 = g_w16[1 * ROW_U4 + i * 8 + l];
        const uint4 w2 = g_w16[2 * ROW_U4 + i * 8 + l];
        u64 pw0[4], pw1[4], pw2[4];
        h8_to_p4(w0, pw0);
        h8_to_p4(w1, pw1);
        h8_to_p4(w2, pw2);

        u64 pA[4], pB[4];
        hprod_to_p4(ua[i],  va[i],  pA);
        hprod_to_p4(ub4[i], vb4[i], pB);
#pragma unroll
        for (int k = 0; k < 4; k++) {
            A0 = ffma2(pA[k], pw0[k], A0);
            A1 = ffma2(pA[k], pw1[k], A1);
            A2 = ffma2(pA[k], pw2[k], A2);
            C0 = ffma2(pB[k], pw0[k], C0);
            C1 = ffma2(pB[k], pw1[k], C1);
            C2 = ffma2(pB[k], pw2[k], C2);
        }
    }

    // Collapse packed lanes, then butterfly over the 8-lane group.
    float a0, a1, a2, c0, c1, c2, lo, hi;
    unpack2(A0, lo, hi); a0 = lo + hi;
    unpack2(A1, lo, hi); a1 = lo + hi;
    unpack2(A2, lo, hi); a2 = lo + hi;
    unpack2(C0, lo, hi); c0 = lo + hi;
    unpack2(C1, lo, hi); c1 = lo + hi;
    unpack2(C2, lo, hi); c2 = lo + hi;

#pragma unroll
    for (int off = 4; off; off >>= 1) {
        a0 += __shfl_xor_sync(0xffffffffu, a0, off);
        a1 += __shfl_xor_sync(0xffffffffu, a1, off);
        a2 += __shfl_xor_sync(0xffffffffu, a2, off);
        c0 += __shfl_xor_sync(0xffffffffu, c0, off);
        c1 += __shfl_xor_sync(0xffffffffu, c1, off);
        c2 += __shfl_xor_sync(0xffffffffu, c2, off);
    }

    if (l < NUM_C) {
        if (val0) {
            float o = fmaf(a0, s0, fmaf(a1, s1, a2 * s2));
            __stcs(out + (size_t)e0 * NUM_C + l, o + ubias0 + vbias0);
        }
        if (val1) {
            float o = fmaf(c0, s0, fmaf(c1, s1, c2 * s2));
            __stcs(out + (size_t)e1 * NUM_C + l, o + ubias1 + vbias1);
        }
    }
}

extern "C" void kernel_launch(void* const* d_in, const int* in_sizes, int n_in,
                              void* d_out, int out_size)
{
    const float* u_feats = (const float*)d_in[0];
    const float* v_feats = (const float*)d_in[1];
    const int*   u_idx   = (const int*)  d_in[2];
    const int*   v_idx   = (const int*)  d_in[3];
    const float* W       = (const float*)d_in[4];
    const float* scalars = (const float*)d_in[5];
    const float* u_bias  = (const float*)d_in[6];
    const float* v_bias  = (const float*)d_in[7];
    float* out = (float*)d_out;

    int E = in_sizes[2];  // u_idx element count

    // Phase 1: convert feature tables + W to fp16 scratch.
    const int n_u = NUM_USERS * ROW_U4;
    const int n_v = NUM_ITEMS * ROW_U4;
    const int n_w = NUM_W * ROW_U4;
    convert_kernel<<<1184, 256>>>(
        reinterpret_cast<const float4*>(u_feats),
        reinterpret_cast<const float4*>(v_feats),
        reinterpret_cast<const float4*>(W),
        n_u, n_v, n_w);

    // Phase 2: main gather kernel.
    int blocks = (E + EDGES_PER_BLOCK - 1) / EDGES_PER_BLOCK;
    bilinear_mixture_kernel<<<blocks, THREADS>>>(
        u_idx, v_idx, scalars, u_bias, v_bias, out, E);
}

// round 14
// speedup vs baseline: 1.1562x; 1.1562x over previous
#include <cuda_runtime.h>
#include <cuda_fp16.h>
#include <cstddef>

// BilinearMixture: out[e,c] = sum_w (sum_d u[ui,d]*W[w,d]*v[vi,d]) * scalars[w,c]
//                           + u_bias[ui,c] + v_bias[vi,c]
// E=2e6, D=128, NUM_W=3, C=5.
//
// Phase 1: convert u/v tables + W to fp16 scratch (51 MB -> L2-resident).
// Phase 2: 8 lanes/edge, 4 groups, 2 edges/thread (8 edges/warp).
//   R12 math (fp32 FMA accumulation; FFMA2 reverted - no pipe gain on sm_103a)
//   restructured for <=64 regs so 4 CTAs/SM fit (32 warps vs 24):
//   - W unpacked per-k (not 24 live floats)
//   - products formed per-k straight from feature uint4s
//   - scalars/bias loaded after compute, covered by the shfl sequence

#define D 128
#define NUM_W 3
#define NUM_C 5
#define NUM_USERS 100000
#define NUM_ITEMS 100000
#define THREADS 256
#define WARPS_PER_BLOCK (THREADS / 32)
#define EDGES_PER_WARP 8
#define EDGES_PER_BLOCK (WARPS_PER_BLOCK * EDGES_PER_WARP)  // 64

#define ROW_U4 (D / 8)            // 16 uint4 per 128-half row
__device__ uint4 g_u16[(size_t)NUM_USERS * ROW_U4];
__device__ uint4 g_v16[(size_t)NUM_ITEMS * ROW_U4];
__device__ uint4 g_w16[NUM_W * ROW_U4];     // 48 uint4

// ---------------- conversion kernel: fp32 -> fp16 ----------------
__global__ __launch_bounds__(256)
void convert_kernel(const float4* __restrict__ u_src,
                    const float4* __restrict__ v_src,
                    const float4* __restrict__ w_src,
                    int n_u, int n_v, int n_w)   // uint4 counts
{
    const int total = n_u + n_v + n_w;
    for (int idx = blockIdx.x * blockDim.x + threadIdx.x; idx < total;
         idx += gridDim.x * blockDim.x)
    {
        const float4* s;
        uint4* dst;
        int j;
        if (idx < n_u)              { s = u_src; dst = g_u16; j = idx; }
        else if (idx < n_u + n_v)   { s = v_src; dst = g_v16; j = idx - n_u; }
        else                        { s = w_src; dst = g_w16; j = idx - n_u - n_v; }
        const float4 a = s[2 * j];
        const float4 b = s[2 * j + 1];
        __half2 h0 = __floats2half2_rn(a.x, a.y);
        __half2 h1 = __floats2half2_rn(a.z, a.w);
        __half2 h2 = __floats2half2_rn(b.x, b.y);
        __half2 h3 = __floats2half2_rn(b.z, b.w);
        uint4 o;
        o.x = *reinterpret_cast<unsigned*>(&h0);
        o.y = *reinterpret_cast<unsigned*>(&h1);
        o.z = *reinterpret_cast<unsigned*>(&h2);
        o.w = *reinterpret_cast<unsigned*>(&h3);
        dst[j] = o;
    }
}

// ---------------- main kernel ----------------
__global__ __launch_bounds__(THREADS, 4)
void bilinear_mixture_kernel(
    const int*   __restrict__ u_idx,
    const int*   __restrict__ v_idx,
    const float* __restrict__ scalars,
    const float* __restrict__ u_bias,
    const float* __restrict__ v_bias,
    float*       __restrict__ out,
    int E)
{
    const int tid  = threadIdx.x;
    const int lane = tid & 31;
    const int l    = lane & 7;        // lane within edge-group (0..7)
    const int g    = lane >> 3;       // edge-group within warp (0..3)
    const int warp = tid >> 5;

    const int ebase = blockIdx.x * EDGES_PER_BLOCK + warp * EDGES_PER_WARP;
    const int e0 = ebase + g;       // quad A edge
    const int e1 = ebase + 4 + g;   // quad B edge
    const bool val0 = (e0 < E);
    const bool val1 = (e1 < E);

    const int ui0 = val0 ? u_idx[e0] : 0;
    const int vi0 = val0 ? v_idx[e0] : 0;
    const int ui1 = val1 ? u_idx[e1] : 0;
    const int vi1 = val1 ? v_idx[e1] : 0;

    // All 8 feature loads issued up front (MLP 8/lane, 4 wf/edge).
    uint4 ua[2], va[2], ub4[2], vb4[2];
#pragma unroll
    for (int i = 0; i < 2; i++) {
        ua[i]  = g_u16[(size_t)ui0 * ROW_U4 + i * 8 + l];
        va[i]  = g_v16[(size_t)vi0 * ROW_U4 + i * 8 + l];
        ub4[i] = g_u16[(size_t)ui1 * ROW_U4 + i * 8 + l];
        vb4[i] = g_v16[(size_t)vi1 * ROW_U4 + i * 8 + l];
    }

    float a0 = 0.f, a1 = 0.f, a2 = 0.f;   // quad A bases
    float c0 = 0.f, c1 = 0.f, c2 = 0.f;   // quad B bases

#pragma unroll
    for (int i = 0; i < 2; i++) {
        // W fp16 broadcast loads (1 wf each); unpack lazily per k.
        const uint4 w0 = g_w16[0 * ROW_U4 + i * 8 + l];
        const uint4 w1 = g_w16[1 * ROW_U4 + i * 8 + l];
        const uint4 w2 = g_w16[2 * ROW_U4 + i * 8 + l];
        const __half2* w0h = reinterpret_cast<const __half2*>(&w0);
        const __half2* w1h = reinterpret_cast<const __half2*>(&w1);
        const __half2* w2h = reinterpret_cast<const __half2*>(&w2);
        const __half2* uah = reinterpret_cast<const __half2*>(&ua[i]);
        const __half2* vah = reinterpret_cast<const __half2*>(&va[i]);
        const __half2* ubh = reinterpret_cast<const __half2*>(&ub4[i]);
        const __half2* vbh = reinterpret_cast<const __half2*>(&vb4[i]);

#pragma unroll
        for (int k = 0; k < 4; k++) {
            const float2 pa = __half22float2(__hmul2(uah[k], vah[k]));
            const float2 pb = __half22float2(__hmul2(ubh[k], vbh[k]));
            const float2 f0 = __half22float2(w0h[k]);
            const float2 f1 = __half22float2(w1h[k]);
            const float2 f2 = __half22float2(w2h[k]);
            a0 = fmaf(pa.x, f0.x, fmaf(pa.y, f0.y, a0));
            a1 = fmaf(pa.x, f1.x, fmaf(pa.y, f1.y, a1));
            a2 = fmaf(pa.x, f2.x, fmaf(pa.y, f2.y, a2));
            c0 = fmaf(pb.x, f0.x, fmaf(pb.y, f0.y, c0));
            c1 = fmaf(pb.x, f1.x, fmaf(pb.y, f1.y, c1));
            c2 = fmaf(pb.x, f2.x, fmaf(pb.y, f2.y, c2));
        }
    }

    // Issue per-class constants + bias gathers now; the shfl sequence below
    // covers their latency.
    float s0 = 0.f, s1 = 0.f, s2 = 0.f;
    float ubias0 = 0.f, vbias0 = 0.f, ubias1 = 0.f, vbias1 = 0.f;
    if (l < NUM_C) {
        s0 = __ldg(scalars + 0 * NUM_C + l);
        s1 = __ldg(scalars + 1 * NUM_C + l);
        s2 = __ldg(scalars + 2 * NUM_C + l);
        ubias0 = __ldg(u_bias + (size_t)ui0 * NUM_C + l);
        vbias0 = __ldg(v_bias + (size_t)vi0 * NUM_C + l);
        ubias1 = __ldg(u_bias + (size_t)ui1 * NUM_C + l);
        vbias1 = __ldg(v_bias + (size_t)vi1 * NUM_C + l);
    }

    // Butterfly over the 8-lane group: 3 rounds x 6 values (2 quads).
#pragma unroll
    for (int off = 4; off; off >>= 1) {
        a0 += __shfl_xor_sync(0xffffffffu, a0, off);
        a1 += __shfl_xor_sync(0xffffffffu, a1, off);
        a2 += __shfl_xor_sync(0xffffffffu, a2, off);
        c0 += __shfl_xor_sync(0xffffffffu, c0, off);
        c1 += __shfl_xor_sync(0xffffffffu, c1, off);
        c2 += __shfl_xor_sync(0xffffffffu, c2, off);
    }

    if (l < NUM_C) {
        if (val0) {
            float o = fmaf(a0, s0, fmaf(a1, s1, a2 * s2));
            __stcs(out + (size_t)e0 * NUM_C + l, o + ubias0 + vbias0);
        }
        if (val1) {
            float o = fmaf(c0, s0, fmaf(c1, s1, c2 * s2));
            __stcs(out + (size_t)e1 * NUM_C + l, o + ubias1 + vbias1);
        }
    }
}

extern "C" void kernel_launch(void* const* d_in, const int* in_sizes, int n_in,
                              void* d_out, int out_size)
{
    const float* u_feats = (const float*)d_in[0];
    const float* v_feats = (const float*)d_in[1];
    const int*   u_idx   = (const int*)  d_in[2];
    const int*   v_idx   = (const int*)  d_in[3];
    const float* W       = (const float*)d_in[4];
    const float* scalars = (const float*)d_in[5];
    const float* u_bias  = (const float*)d_in[6];
    const float* v_bias  = (const float*)d_in[7];
    float* out = (float*)d_out;

    int E = in_sizes[2];  // u_idx element count

    // Phase 1: convert feature tables + W to fp16 scratch.
    const int n_u = NUM_USERS * ROW_U4;
    const int n_v = NUM_ITEMS * ROW_U4;
    const int n_w = NUM_W * ROW_U4;
    convert_kernel<<<1184, 256>>>(
        reinterpret_cast<const float4*>(u_feats),
        reinterpret_cast<const float4*>(v_feats),
        reinterpret_cast<const float4*>(W),
        n_u, n_v, n_w);

    // Phase 2: main gather kernel.
    int blocks = (E + EDGES_PER_BLOCK - 1) / EDGES_PER_BLOCK;
    bilinear_mixture_kernel<<<blocks, THREADS>>>(
        u_idx, v_idx, scalars, u_bias, v_bias, out, E);
}

// round 15
// speedup vs baseline: 1.2400x; 1.0725x over previous
#include <cuda_runtime.h>
#include <cuda_fp16.h>
#include <cstddef>

// BilinearMixture: out[e,c] = sum_w (sum_d u[ui,d]*W[w,d]*v[vi,d]) * scalars[w,c]
//                           + u_bias[ui,c] + v_bias[vi,c]
// E=2e6, D=128, NUM_W=3, C=5.
//
// Phase 1: convert u/v tables + W to fp16 scratch (51 MB -> L2-resident).
// Phase 2: 8 lanes/edge, 4 groups, 2 edges/thread (8 edges/warp).
//   R14 structure, but the inner accumulation stays in fp16:
//   per i: p_k = hmul2(u,v); basis-accum via hfma2 chains (4 terms), then ONE
//   flush to fp32 per i. Kills all W-unpack F2F and most product F2F:
//   loop math 192 -> 112 ops per lane per 2 edges. Guard-free path when
//   E % 64 == 0 (true for this problem) removes predication.

#define D 128
#define NUM_W 3
#define NUM_C 5
#define NUM_USERS 100000
#define NUM_ITEMS 100000
#define THREADS 256
#define WARPS_PER_BLOCK (THREADS / 32)
#define EDGES_PER_WARP 8
#define EDGES_PER_BLOCK (WARPS_PER_BLOCK * EDGES_PER_WARP)  // 64

#define ROW_U4 (D / 8)            // 16 uint4 per 128-half row
__device__ uint4 g_u16[(size_t)NUM_USERS * ROW_U4];
__device__ uint4 g_v16[(size_t)NUM_ITEMS * ROW_U4];
__device__ uint4 g_w16[NUM_W * ROW_U4];     // 48 uint4

// ---------------- conversion kernel: fp32 -> fp16 ----------------
__global__ __launch_bounds__(256)
void convert_kernel(const float4* __restrict__ u_src,
                    const float4* __restrict__ v_src,
                    const float4* __restrict__ w_src,
                    int n_u, int n_v, int n_w)   // uint4 counts
{
    const int total = n_u + n_v + n_w;
    for (int idx = blockIdx.x * blockDim.x + threadIdx.x; idx < total;
         idx += gridDim.x * blockDim.x)
    {
        const float4* s;
        uint4* dst;
        int j;
        if (idx < n_u)              { s = u_src; dst = g_u16; j = idx; }
        else if (idx < n_u + n_v)   { s = v_src; dst = g_v16; j = idx - n_u; }
        else                        { s = w_src; dst = g_w16; j = idx - n_u - n_v; }
        const float4 a = s[2 * j];
        const float4 b = s[2 * j + 1];
        __half2 h0 = __floats2half2_rn(a.x, a.y);
        __half2 h1 = __floats2half2_rn(a.z, a.w);
        __half2 h2 = __floats2half2_rn(b.x, b.y);
        __half2 h3 = __floats2half2_rn(b.z, b.w);
        uint4 o;
        o.x = *reinterpret_cast<unsigned*>(&h0);
        o.y = *reinterpret_cast<unsigned*>(&h1);
        o.z = *reinterpret_cast<unsigned*>(&h2);
        o.w = *reinterpret_cast<unsigned*>(&h3);
        dst[j] = o;
    }
}

// ---------------- main kernel ----------------
template <bool GUARD>
__global__ __launch_bounds__(THREADS, 4)
void bilinear_mixture_kernel(
    const int*   __restrict__ u_idx,
    const int*   __restrict__ v_idx,
    const float* __restrict__ scalars,
    const float* __restrict__ u_bias,
    const float* __restrict__ v_bias,
    float*       __restrict__ out,
    int E)
{
    const int tid  = threadIdx.x;
    const int lane = tid & 31;
    const int l    = lane & 7;        // lane within edge-group (0..7)
    const int g    = lane >> 3;       // edge-group within warp (0..3)
    const int warp = tid >> 5;

    const int ebase = blockIdx.x * EDGES_PER_BLOCK + warp * EDGES_PER_WARP;
    const int e0 = ebase + g;       // quad A edge
    const int e1 = ebase + 4 + g;   // quad B edge
    bool val0 = true, val1 = true;
    if (GUARD) { val0 = (e0 < E); val1 = (e1 < E); }

    const int ui0 = val0 ? u_idx[e0] : 0;
    const int vi0 = val0 ? v_idx[e0] : 0;
    const int ui1 = val1 ? u_idx[e1] : 0;
    const int vi1 = val1 ? v_idx[e1] : 0;

    // All 8 feature loads issued up front (MLP 8/lane, 4 wf/edge).
    uint4 ua[2], va[2], ub4[2], vb4[2];
#pragma unroll
    for (int i = 0; i < 2; i++) {
        ua[i]  = g_u16[(size_t)ui0 * ROW_U4 + i * 8 + l];
        va[i]  = g_v16[(size_t)vi0 * ROW_U4 + i * 8 + l];
        ub4[i] = g_u16[(size_t)ui1 * ROW_U4 + i * 8 + l];
        vb4[i] = g_v16[(size_t)vi1 * ROW_U4 + i * 8 + l];
    }

    float a0 = 0.f, a1 = 0.f, a2 = 0.f;   // quad A bases (fp32)
    float c0 = 0.f, c1 = 0.f, c2 = 0.f;   // quad B bases (fp32)

#pragma unroll
    for (int i = 0; i < 2; i++) {
        // W fp16 broadcast loads (1 wf each); stay in fp16.
        const uint4 w0 = g_w16[0 * ROW_U4 + i * 8 + l];
        const uint4 w1 = g_w16[1 * ROW_U4 + i * 8 + l];
        const uint4 w2 = g_w16[2 * ROW_U4 + i * 8 + l];
        const __half2* w0h = reinterpret_cast<const __half2*>(&w0);
        const __half2* w1h = reinterpret_cast<const __half2*>(&w1);
        const __half2* w2h = reinterpret_cast<const __half2*>(&w2);
        const __half2* uah = reinterpret_cast<const __half2*>(&ua[i]);
        const __half2* vah = reinterpret_cast<const __half2*>(&va[i]);
        const __half2* ubh = reinterpret_cast<const __half2*>(&ub4[i]);
        const __half2* vbh = reinterpret_cast<const __half2*>(&vb4[i]);

        // Products in fp16 (rounding already in the existing error budget).
        __half2 pa[4], pb[4];
#pragma unroll
        for (int k = 0; k < 4; k++) {
            pa[k] = __hmul2(uah[k], vah[k]);
            pb[k] = __hmul2(ubh[k], vbh[k]);
        }

        // fp16 accumulation over the 4 k-terms (3 rounded adds per partial),
        // flushed to fp32 once per i.
        __half2 hA0 = __hmul2(pa[0], w0h[0]);
        __half2 hA1 = __hmul2(pa[0], w1h[0]);
        __half2 hA2 = __hmul2(pa[0], w2h[0]);
        __half2 hB0 = __hmul2(pb[0], w0h[0]);
        __half2 hB1 = __hmul2(pb[0], w1h[0]);
        __half2 hB2 = __hmul2(pb[0], w2h[0]);
#pragma unroll
        for (int k = 1; k < 4; k++) {
            hA0 = __hfma2(pa[k], w0h[k], hA0);
            hA1 = __hfma2(pa[k], w1h[k], hA1);
            hA2 = __hfma2(pa[k], w2h[k], hA2);
            hB0 = __hfma2(pb[k], w0h[k], hB0);
            hB1 = __hfma2(pb[k], w1h[k], hB1);
            hB2 = __hfma2(pb[k], w2h[k], hB2);
        }

        float2 t;
        t = __half22float2(hA0); a0 += t.x + t.y;
        t = __half22float2(hA1); a1 += t.x + t.y;
        t = __half22float2(hA2); a2 += t.x + t.y;
        t = __half22float2(hB0); c0 += t.x + t.y;
        t = __half22float2(hB1); c1 += t.x + t.y;
        t = __half22float2(hB2); c2 += t.x + t.y;
    }

    // Per-class constants + bias gathers; covered by the shfl sequence.
    float s0 = 0.f, s1 = 0.f, s2 = 0.f;
    float ubias0 = 0.f, vbias0 = 0.f, ubias1 = 0.f, vbias1 = 0.f;
    if (l < NUM_C) {
        s0 = __ldg(scalars + 0 * NUM_C + l);
        s1 = __ldg(scalars + 1 * NUM_C + l);
        s2 = __ldg(scalars + 2 * NUM_C + l);
        ubias0 = __ldg(u_bias + (size_t)ui0 * NUM_C + l);
        vbias0 = __ldg(v_bias + (size_t)vi0 * NUM_C + l);
        ubias1 = __ldg(u_bias + (size_t)ui1 * NUM_C + l);
        vbias1 = __ldg(v_bias + (size_t)vi1 * NUM_C + l);
    }

    // Butterfly over the 8-lane group: 3 rounds x 6 values (fp32).
#pragma unroll
    for (int off = 4; off; off >>= 1) {
        a0 += __shfl_xor_sync(0xffffffffu, a0, off);
        a1 += __shfl_xor_sync(0xffffffffu, a1, off);
        a2 += __shfl_xor_sync(0xffffffffu, a2, off);
        c0 += __shfl_xor_sync(0xffffffffu, c0, off);
        c1 += __shfl_xor_sync(0xffffffffu, c1, off);
        c2 += __shfl_xor_sync(0xffffffffu, c2, off);
    }

    if (l < NUM_C) {
        if (!GUARD || val0) {
            float o = fmaf(a0, s0, fmaf(a1, s1, a2 * s2));
            __stcs(out + (size_t)e0 * NUM_C + l, o + ubias0 + vbias0);
        }
        if (!GUARD || val1) {
            float o = fmaf(c0, s0, fmaf(c1, s1, c2 * s2));
            __stcs(out + (size_t)e1 * NUM_C + l, o + ubias1 + vbias1);
        }
    }
}

extern "C" void kernel_launch(void* const* d_in, const int* in_sizes, int n_in,
                              void* d_out, int out_size)
{
    const float* u_feats = (const float*)d_in[0];
    const float* v_feats = (const float*)d_in[1];
    const int*   u_idx   = (const int*)  d_in[2];
    const int*   v_idx   = (const int*)  d_in[3];
    const float* W       = (const float*)d_in[4];
    const float* scalars = (const float*)d_in[5];
    const float* u_bias  = (const float*)d_in[6];
    const float* v_bias  = (const float*)d_in[7];
    float* out = (float*)d_out;

    int E = in_sizes[2];  // u_idx element count

    // Phase 1: convert feature tables + W to fp16 scratch.
    const int n_u = NUM_USERS * ROW_U4;
    const int n_v = NUM_ITEMS * ROW_U4;
    const int n_w = NUM_W * ROW_U4;
    convert_kernel<<<1184, 256>>>(
        reinterpret_cast<const float4*>(u_feats),
        reinterpret_cast<const float4*>(v_feats),
        reinterpret_cast<const float4*>(W),
        n_u, n_v, n_w);

    // Phase 2: main gather kernel (guard-free when E divides evenly).
    int blocks = (E + EDGES_PER_BLOCK - 1) / EDGES_PER_BLOCK;
    if (E % EDGES_PER_BLOCK == 0) {
        bilinear_mixture_kernel<false><<<blocks, THREADS>>>(
            u_idx, v_idx, scalars, u_bias, v_bias, out, E);
    } else {
        bilinear_mixture_kernel<true><<<blocks, THREADS>>>(
            u_idx, v_idx, scalars, u_bias, v_bias, out, E);
    }
}

// round 16
// speedup vs baseline: 1.3014x; 1.0495x over previous
#include <cuda_runtime.h>
#include <cuda_fp16.h>
#include <cstddef>

// BilinearMixture: out[e,c] = sum_w (sum_d u[ui,d]*W[w,d]*v[vi,d]) * scalars[w,c]
//                           + u_bias[ui,c] + v_bias[vi,c]
// E=2e6, D=128, NUM_W=3, C=5.
//
// Phase 1: convert u/v tables + W to fp16 scratch (51 MB -> L2-resident).
// Phase 2: 8 lanes/edge, 4 groups, 2 edges/thread (8 edges/warp).
//   R15 + two tweaks:
//   - fp16 accumulators carried across BOTH i-iterations (8-term hfma2
//     chains, single flush): -24 ops per lane per 2 edges
//   - bias gathers issued right after feature loads (latency overlapped by
//     the compute loop instead of exposed in the tail)

#define D 128
#define NUM_W 3
#define NUM_C 5
#define NUM_USERS 100000
#define NUM_ITEMS 100000
#define THREADS 256
#define WARPS_PER_BLOCK (THREADS / 32)
#define EDGES_PER_WARP 8
#define EDGES_PER_BLOCK (WARPS_PER_BLOCK * EDGES_PER_WARP)  // 64

#define ROW_U4 (D / 8)            // 16 uint4 per 128-half row
__device__ uint4 g_u16[(size_t)NUM_USERS * ROW_U4];
__device__ uint4 g_v16[(size_t)NUM_ITEMS * ROW_U4];
__device__ uint4 g_w16[NUM_W * ROW_U4];     // 48 uint4

// ---------------- conversion kernel: fp32 -> fp16 ----------------
__global__ __launch_bounds__(256)
void convert_kernel(const float4* __restrict__ u_src,
                    const float4* __restrict__ v_src,
                    const float4* __restrict__ w_src,
                    int n_u, int n_v, int n_w)   // uint4 counts
{
    const int total = n_u + n_v + n_w;
    for (int idx = blockIdx.x * blockDim.x + threadIdx.x; idx < total;
         idx += gridDim.x * blockDim.x)
    {
        const float4* s;
        uint4* dst;
        int j;
        if (idx < n_u)              { s = u_src; dst = g_u16; j = idx; }
        else if (idx < n_u + n_v)   { s = v_src; dst = g_v16; j = idx - n_u; }
        else                        { s = w_src; dst = g_w16; j = idx - n_u - n_v; }
        const float4 a = s[2 * j];
        const float4 b = s[2 * j + 1];
        __half2 h0 = __floats2half2_rn(a.x, a.y);
        __half2 h1 = __floats2half2_rn(a.z, a.w);
        __half2 h2 = __floats2half2_rn(b.x, b.y);
        __half2 h3 = __floats2half2_rn(b.z, b.w);
        uint4 o;
        o.x = *reinterpret_cast<unsigned*>(&h0);
        o.y = *reinterpret_cast<unsigned*>(&h1);
        o.z = *reinterpret_cast<unsigned*>(&h2);
        o.w = *reinterpret_cast<unsigned*>(&h3);
        dst[j] = o;
    }
}

// ---------------- main kernel ----------------
template <bool GUARD>
__global__ __launch_bounds__(THREADS, 4)
void bilinear_mixture_kernel(
    const int*   __restrict__ u_idx,
    const int*   __restrict__ v_idx,
    const float* __restrict__ scalars,
    const float* __restrict__ u_bias,
    const float* __restrict__ v_bias,
    float*       __restrict__ out,
    int E)
{
    const int tid  = threadIdx.x;
    const int lane = tid & 31;
    const int l    = lane & 7;        // lane within edge-group (0..7)
    const int g    = lane >> 3;       // edge-group within warp (0..3)
    const int warp = tid >> 5;

    const int ebase = blockIdx.x * EDGES_PER_BLOCK + warp * EDGES_PER_WARP;
    const int e0 = ebase + g;       // quad A edge
    const int e1 = ebase + 4 + g;   // quad B edge
    bool val0 = true, val1 = true;
    if (GUARD) { val0 = (e0 < E); val1 = (e1 < E); }

    const int ui0 = val0 ? u_idx[e0] : 0;
    const int vi0 = val0 ? v_idx[e0] : 0;
    const int ui1 = val1 ? u_idx[e1] : 0;
    const int vi1 = val1 ? v_idx[e1] : 0;

    // All 8 feature loads issued up front (MLP 8/lane, 4 wf/edge).
    uint4 ua[2], va[2], ub4[2], vb4[2];
#pragma unroll
    for (int i = 0; i < 2; i++) {
        ua[i]  = g_u16[(size_t)ui0 * ROW_U4 + i * 8 + l];
        va[i]  = g_v16[(size_t)vi0 * ROW_U4 + i * 8 + l];
        ub4[i] = g_u16[(size_t)ui1 * ROW_U4 + i * 8 + l];
        vb4[i] = g_v16[(size_t)vi1 * ROW_U4 + i * 8 + l];
    }

    // Bias gathers issued NOW: their latency hides under the compute loop.
    float ubias0 = 0.f, vbias0 = 0.f, ubias1 = 0.f, vbias1 = 0.f;
    if (l < NUM_C) {
        ubias0 = __ldg(u_bias + (size_t)ui0 * NUM_C + l);
        vbias0 = __ldg(v_bias + (size_t)vi0 * NUM_C + l);
        ubias1 = __ldg(u_bias + (size_t)ui1 * NUM_C + l);
        vbias1 = __ldg(v_bias + (size_t)vi1 * NUM_C + l);
    }

    // fp16 accumulators carried across both i-iterations (8-term chains).
    __half2 hA0, hA1, hA2, hB0, hB1, hB2;
    {
        const __half2 z = __float2half2_rn(0.f);
        hA0 = z; hA1 = z; hA2 = z; hB0 = z; hB1 = z; hB2 = z;
    }

#pragma unroll
    for (int i = 0; i < 2; i++) {
        // W fp16 broadcast loads (1 wf each); stay in fp16.
        const uint4 w0 = g_w16[0 * ROW_U4 + i * 8 + l];
        const uint4 w1 = g_w16[1 * ROW_U4 + i * 8 + l];
        const uint4 w2 = g_w16[2 * ROW_U4 + i * 8 + l];
        const __half2* w0h = reinterpret_cast<const __half2*>(&w0);
        const __half2* w1h = reinterpret_cast<const __half2*>(&w1);
        const __half2* w2h = reinterpret_cast<const __half2*>(&w2);
        const __half2* uah = reinterpret_cast<const __half2*>(&ua[i]);
        const __half2* vah = reinterpret_cast<const __half2*>(&va[i]);
        const __half2* ubh = reinterpret_cast<const __half2*>(&ub4[i]);
        const __half2* vbh = reinterpret_cast<const __half2*>(&vb4[i]);

#pragma unroll
        for (int k = 0; k < 4; k++) {
            const __half2 pa = __hmul2(uah[k], vah[k]);
            const __half2 pb = __hmul2(ubh[k], vbh[k]);
            hA0 = __hfma2(pa, w0h[k], hA0);
            hA1 = __hfma2(pa, w1h[k], hA1);
            hA2 = __hfma2(pa, w2h[k], hA2);
            hB0 = __hfma2(pb, w0h[k], hB0);
            hB1 = __hfma2(pb, w1h[k], hB1);
            hB2 = __hfma2(pb, w2h[k], hB2);
        }
    }

    // Single flush to fp32.
    float a0, a1, a2, c0, c1, c2;
    {
        float2 t;
        t = __half22float2(hA0); a0 = t.x + t.y;
        t = __half22float2(hA1); a1 = t.x + t.y;
        t = __half22float2(hA2); a2 = t.x + t.y;
        t = __half22float2(hB0); c0 = t.x + t.y;
        t = __half22float2(hB1); c1 = t.x + t.y;
        t = __half22float2(hB2); c2 = t.x + t.y;
    }

    // Per-class mix constants (L1-hit broadcast; cheap in the tail).
    float s0 = 0.f, s1 = 0.f, s2 = 0.f;
    if (l < NUM_C) {
        s0 = __ldg(scalars + 0 * NUM_C + l);
        s1 = __ldg(scalars + 1 * NUM_C + l);
        s2 = __ldg(scalars + 2 * NUM_C + l);
    }

    // Butterfly over the 8-lane group: 3 rounds x 6 values (fp32).
#pragma unroll
    for (int off = 4; off; off >>= 1) {
        a0 += __shfl_xor_sync(0xffffffffu, a0, off);
        a1 += __shfl_xor_sync(0xffffffffu, a1, off);
        a2 += __shfl_xor_sync(0xffffffffu, a2, off);
        c0 += __shfl_xor_sync(0xffffffffu, c0, off);
        c1 += __shfl_xor_sync(0xffffffffu, c1, off);
        c2 += __shfl_xor_sync(0xffffffffu, c2, off);
    }

    if (l < NUM_C) {
        if (!GUARD || val0) {
            float o = fmaf(a0, s0, fmaf(a1, s1, a2 * s2));
            __stcs(out + (size_t)e0 * NUM_C + l, o + ubias0 + vbias0);
        }
        if (!GUARD || val1) {
            float o = fmaf(c0, s0, fmaf(c1, s1, c2 * s2));
            __stcs(out + (size_t)e1 * NUM_C + l, o + ubias1 + vbias1);
        }
    }
}

extern "C" void kernel_launch(void* const* d_in, const int* in_sizes, int n_in,
                              void* d_out, int out_size)
{
    const float* u_feats = (const float*)d_in[0];
    const float* v_feats = (const float*)d_in[1];
    const int*   u_idx   = (const int*)  d_in[2];
    const int*   v_idx   = (const int*)  d_in[3];
    const float* W       = (const float*)d_in[4];
    const float* scalars = (const float*)d_in[5];
    const float* u_bias  = (const float*)d_in[6];
    const float* v_bias  = (const float*)d_in[7];
    float* out = (float*)d_out;

    int E = in_sizes[2];  // u_idx element count

    // Phase 1: convert feature tables + W to fp16 scratch.
    const int n_u = NUM_USERS * ROW_U4;
    const int n_v = NUM_ITEMS * ROW_U4;
    const int n_w = NUM_W * ROW_U4;
    convert_kernel<<<1184, 256>>>(
        reinterpret_cast<const float4*>(u_feats),
        reinterpret_cast<const float4*>(v_feats),
        reinterpret_cast<const float4*>(W),
        n_u, n_v, n_w);

    // Phase 2: main gather kernel (guard-free when E divides evenly).
    int blocks = (E + EDGES_PER_BLOCK - 1) / EDGES_PER_BLOCK;
    if (E % EDGES_PER_BLOCK == 0) {
        bilinear_mixture_kernel<false><<<blocks, THREADS>>>(
            u_idx, v_idx, scalars, u_bias, v_bias, out, E);
    } else {
        bilinear_mixture_kernel<true><<<blocks, THREADS>>>(
            u_idx, v_idx, scalars, u_bias, v_bias, out, E);
    }
}